// round 3
// baseline (speedup 1.0000x reference)
#include <cuda_runtime.h>

// Ultimus R3: f32x2 lanes = 2 output rows; keys duplicated in smem so LDS.128
// feeds 2 keys/load. proj de-spilled + 3-way grid. KSPLIT=16.

#define NROWS 8192
#define DIN   48
#define DA    8
#define KSPLIT 16
#define RPB   256   // output rows per attn block
#define TK    128

typedef unsigned long long u64;

__device__ __align__(16) float g_k[NROWS * DA];   // Xk * (log2e / sqrt(8))
__device__ __align__(16) float g_q[NROWS * DA];
__device__ __align__(16) float g_v[NROWS * DA];
__device__ __align__(16) float g_acc[KSPLIT * NROWS * DA];
__device__ __align__(16) float g_sum[KSPLIT * NROWS];

// ---- f32x2 helpers ----
__device__ __forceinline__ u64 fma2(u64 a, u64 b, u64 c) {
    u64 d; asm("fma.rn.f32x2 %0, %1, %2, %3;" : "=l"(d) : "l"(a), "l"(b), "l"(c)); return d;
}
__device__ __forceinline__ u64 mul2(u64 a, u64 b) {
    u64 d; asm("mul.rn.f32x2 %0, %1, %2;" : "=l"(d) : "l"(a), "l"(b)); return d;
}
__device__ __forceinline__ u64 add2(u64 a, u64 b) {
    u64 d; asm("add.rn.f32x2 %0, %1, %2;" : "=l"(d) : "l"(a), "l"(b)); return d;
}
__device__ __forceinline__ u64 pack2(float lo, float hi) {
    u64 d; asm("mov.b64 %0, {%1, %2};" : "=l"(d) : "f"(lo), "f"(hi)); return d;
}
__device__ __forceinline__ float2 unpack2(u64 v) {
    float2 r; asm("mov.b64 {%0, %1}, %2;" : "=f"(r.x), "=f"(r.y) : "l"(v)); return r;
}
__device__ __forceinline__ u64 ex2_2(u64 s) {
    u64 p;
    asm("{\n\t"
        ".reg .f32 lo, hi, pl, ph;\n\t"
        "mov.b64 {lo, hi}, %1;\n\t"
        "ex2.approx.ftz.f32 pl, lo;\n\t"
        "ex2.approx.ftz.f32 ph, hi;\n\t"
        "mov.b64 %0, {pl, ph};\n\t"
        "}" : "=l"(p) : "l"(s));
    return p;
}

// ---------------- Kernel 1: QKV projections (grid.y selects K/Q/V) ----------------
__global__ __launch_bounds__(128) void proj_kernel(
    const float* __restrict__ x,
    const float* __restrict__ Kw, const float* __restrict__ Kb,
    const float* __restrict__ Qw, const float* __restrict__ Qb,
    const float* __restrict__ Vw, const float* __restrict__ Vb)
{
    __shared__ float sW[DIN * DA];
    __shared__ float sB[DA];
    int t = threadIdx.x;
    int which = blockIdx.y;
    const float* W = (which == 0) ? Kw : (which == 1) ? Qw : Vw;
    const float* B = (which == 0) ? Kb : (which == 1) ? Qb : Vb;
    for (int i = t; i < DIN * DA; i += 128) sW[i] = W[i];
    if (t < DA) sB[t] = B[t];
    __syncthreads();

    // K gets log2(e)/sqrt(8) folded in
    float scale = (which == 0) ? (1.4426950408889634f / 2.8284271247461903f) : 1.0f;

    int row = blockIdx.x * 128 + t;
    const float4* xp = (const float4*)(x + (size_t)row * DIN);

    float acc[DA];
#pragma unroll
    for (int a = 0; a < DA; a++) acc[a] = sB[a];

#pragma unroll
    for (int c = 0; c < DIN / 4; c++) {
        float4 x4 = xp[c];
        float xe[4] = {x4.x, x4.y, x4.z, x4.w};
#pragma unroll
        for (int e = 0; e < 4; e++) {
            float xv = xe[e];
            const float* w = &sW[(4 * c + e) * DA];
#pragma unroll
            for (int a = 0; a < DA; a++) acc[a] = fmaf(xv, w[a], acc[a]);
        }
    }

    float* dst = (which == 0) ? g_k : (which == 1) ? g_q : g_v;
    float4* op = (float4*)(dst + (size_t)row * DA);
    op[0] = make_float4(acc[0] * scale, acc[1] * scale, acc[2] * scale, acc[3] * scale);
    op[1] = make_float4(acc[4] * scale, acc[5] * scale, acc[6] * scale, acc[7] * scale);
}

// ---------------- Kernel 2: attention, lanes = 2 rows, keys duplicated in smem ----------------
__global__ __launch_bounds__(128) void attn_kernel()
{
    __shared__ __align__(16) u64 dupQ[DA * TK];  // dupQ[d*TK + j] = {Xq_j[d], Xq_j[d]}
    __shared__ __align__(16) u64 dupV[DA * TK];

    int t = threadIdx.x;
    int r0 = blockIdx.x * RPB + 2 * t;      // thread handles rows r0, r0+1

    // load the two rows' Xk (contiguous 64B)
    const float4* kp = (const float4*)(g_k + (size_t)r0 * DA);
    float4 ka0 = kp[0], kb0 = kp[1], ka1 = kp[2], kb1 = kp[3];
    u64 kk[DA];
    kk[0] = pack2(ka0.x, ka1.x); kk[1] = pack2(ka0.y, ka1.y);
    kk[2] = pack2(ka0.z, ka1.z); kk[3] = pack2(ka0.w, ka1.w);
    kk[4] = pack2(kb0.x, kb1.x); kk[5] = pack2(kb0.y, kb1.y);
    kk[6] = pack2(kb0.z, kb1.z); kk[7] = pack2(kb0.w, kb1.w);

    u64 acc[DA];
#pragma unroll
    for (int a = 0; a < DA; a++) acc[a] = 0ULL;
    u64 ssum = 0ULL;

    int kbase = blockIdx.y * (NROWS / KSPLIT);

    for (int b = kbase; b < kbase + NROWS / KSPLIT; b += TK) {
        __syncthreads();
        {
            const float4* gq = (const float4*)(g_q + (size_t)(b + t) * DA);
            const float4* gv = (const float4*)(g_v + (size_t)(b + t) * DA);
            float4 qa = gq[0], qb = gq[1];
            float4 va = gv[0], vb = gv[1];
            dupQ[0 * TK + t] = pack2(qa.x, qa.x); dupQ[1 * TK + t] = pack2(qa.y, qa.y);
            dupQ[2 * TK + t] = pack2(qa.z, qa.z); dupQ[3 * TK + t] = pack2(qa.w, qa.w);
            dupQ[4 * TK + t] = pack2(qb.x, qb.x); dupQ[5 * TK + t] = pack2(qb.y, qb.y);
            dupQ[6 * TK + t] = pack2(qb.z, qb.z); dupQ[7 * TK + t] = pack2(qb.w, qb.w);
            dupV[0 * TK + t] = pack2(va.x, va.x); dupV[1 * TK + t] = pack2(va.y, va.y);
            dupV[2 * TK + t] = pack2(va.z, va.z); dupV[3 * TK + t] = pack2(va.w, va.w);
            dupV[4 * TK + t] = pack2(vb.x, vb.x); dupV[5 * TK + t] = pack2(vb.y, vb.y);
            dupV[6 * TK + t] = pack2(vb.z, vb.z); dupV[7 * TK + t] = pack2(vb.w, vb.w);
        }
        __syncthreads();

        const ulonglong2* q2 = (const ulonglong2*)dupQ;  // [DA][TK/2]
        const ulonglong2* v2 = (const ulonglong2*)dupV;

#pragma unroll 4
        for (int j2 = 0; j2 < TK / 2; j2++) {
            u64 sA, sB;
            {
                ulonglong2 qd = q2[0 * (TK / 2) + j2];
                sA = mul2(kk[0], qd.x);
                sB = mul2(kk[0], qd.y);
            }
#pragma unroll
            for (int d = 1; d < DA; d++) {
                ulonglong2 qd = q2[d * (TK / 2) + j2];
                sA = fma2(kk[d], qd.x, sA);
                sB = fma2(kk[d], qd.y, sB);
            }
            u64 pA = ex2_2(sA);
            u64 pB = ex2_2(sB);
            ssum = add2(ssum, add2(pA, pB));
#pragma unroll
            for (int a = 0; a < DA; a++) {
                ulonglong2 vd = v2[a * (TK / 2) + j2];
                acc[a] = fma2(pA, vd.x, acc[a]);
                acc[a] = fma2(pB, vd.y, acc[a]);
            }
        }
    }

    int o0 = blockIdx.y * NROWS + r0;
    float2 su = unpack2(ssum);
    g_sum[o0] = su.x;
    g_sum[o0 + 1] = su.y;

    float2 u0 = unpack2(acc[0]), u1 = unpack2(acc[1]), u2 = unpack2(acc[2]), u3 = unpack2(acc[3]);
    float2 u4 = unpack2(acc[4]), u5 = unpack2(acc[5]), u6 = unpack2(acc[6]), u7 = unpack2(acc[7]);
    float4* ap = (float4*)(g_acc + (size_t)o0 * DA);
    ap[0] = make_float4(u0.x, u1.x, u2.x, u3.x);
    ap[1] = make_float4(u4.x, u5.x, u6.x, u7.x);
    ap[2] = make_float4(u0.y, u1.y, u2.y, u3.y);
    ap[3] = make_float4(u4.y, u5.y, u6.y, u7.y);
}

// ---------------- Kernel 3: reduce + normalize + output proj + residual ----------------
__global__ __launch_bounds__(128) void final_kernel(
    const float* __restrict__ x,
    const float* __restrict__ Zw, const float* __restrict__ Zb,
    float* __restrict__ out)
{
    __shared__ float sZ[DA * DIN];
    __shared__ float sZb[DIN];
    int t = threadIdx.x;
    for (int i = t; i < DA * DIN; i += 128) sZ[i] = Zw[i];
    if (t < DIN) sZb[t] = Zb[t];
    __syncthreads();

    int row = blockIdx.x * 128 + t;

    float acc[DA];
#pragma unroll
    for (int a = 0; a < DA; a++) acc[a] = 0.0f;
    float ssum = 0.0f;
#pragma unroll
    for (int s = 0; s < KSPLIT; s++) {
        int o = s * NROWS + row;
        ssum += g_sum[o];
        const float4* ap = (const float4*)(g_acc + (size_t)o * DA);
        float4 a0 = ap[0], a1 = ap[1];
        acc[0] += a0.x; acc[1] += a0.y; acc[2] += a0.z; acc[3] += a0.w;
        acc[4] += a1.x; acc[5] += a1.y; acc[6] += a1.z; acc[7] += a1.w;
    }
    float inv = 1.0f / ssum;
    float z[DA];
#pragma unroll
    for (int a = 0; a < DA; a++) z[a] = acc[a] * inv;

    const float4* xp = (const float4*)(x + (size_t)row * DIN);
    float4* op = (float4*)(out + (size_t)row * DIN);

#pragma unroll
    for (int ch = 0; ch < DIN / 8; ch++) {
        float4 xa = xp[2 * ch], xb = xp[2 * ch + 1];
        float o8[8];
        o8[0] = xa.x + sZb[8 * ch + 0]; o8[1] = xa.y + sZb[8 * ch + 1];
        o8[2] = xa.z + sZb[8 * ch + 2]; o8[3] = xa.w + sZb[8 * ch + 3];
        o8[4] = xb.x + sZb[8 * ch + 4]; o8[5] = xb.y + sZb[8 * ch + 5];
        o8[6] = xb.z + sZb[8 * ch + 6]; o8[7] = xb.w + sZb[8 * ch + 7];
#pragma unroll
        for (int a = 0; a < DA; a++) {
            float za = z[a];
            const float* w = &sZ[a * DIN + 8 * ch];
#pragma unroll
            for (int e = 0; e < 8; e++) o8[e] = fmaf(za, w[e], o8[e]);
        }
        op[2 * ch]     = make_float4(o8[0], o8[1], o8[2], o8[3]);
        op[2 * ch + 1] = make_float4(o8[4], o8[5], o8[6], o8[7]);
    }
}

extern "C" void kernel_launch(void* const* d_in, const int* in_sizes, int n_in,
                              void* d_out, int out_size)
{
    (void)in_sizes; (void)n_in; (void)out_size;
    const float* x  = (const float*)d_in[0];
    const float* Kw = (const float*)d_in[1];
    const float* Kb = (const float*)d_in[2];
    const float* Qw = (const float*)d_in[3];
    const float* Qb = (const float*)d_in[4];
    const float* Vw = (const float*)d_in[5];
    const float* Vb = (const float*)d_in[6];
    const float* Zw = (const float*)d_in[7];
    const float* Zb = (const float*)d_in[8];
    float* out = (float*)d_out;

    dim3 gp(NROWS / 128, 3);
    proj_kernel<<<gp, 128>>>(x, Kw, Kb, Qw, Qb, Vw, Vb);
    dim3 ga(NROWS / RPB, KSPLIT);
    attn_kernel<<<ga, 128>>>();
    final_kernel<<<NROWS / 128, 128>>>(x, Zw, Zb, out);
}

// round 5
// speedup vs baseline: 1.3400x; 1.3400x over previous
#include <cuda_runtime.h>
#include <cuda_fp16.h>
#include <cstdint>

// Ultimus R5: fp16x2 (HFMA2) attention — 2 keys per lane-pair, full-rate fma pipe.
// exp via ex2.approx.f16x2 (log2e/sqrt(8) folded into Xk). Per-chunk fp16 accumulators
// drained to fp32. No max-subtraction (logits bounded), key-split partials additive.

#define NROWS 8192
#define DIN   48
#define DA    8
#define KSPLIT 8
#define QTILE 128            // q-rows per attn block (1/thread)
#define CHUNK 128            // keys staged per smem tile
#define NCHUNKS ((NROWS / KSPLIT) / CHUNK)   // 8

typedef unsigned int u32;

__device__ __align__(16) __half g_k[NROWS * DA];   // Xk * log2e/sqrt(8)
__device__ __align__(16) __half g_q[NROWS * DA];
__device__ __align__(16) __half g_v[NROWS * DA];
__device__ __align__(16) float g_acc[KSPLIT * NROWS * DA];
__device__ float g_sum[KSPLIT * NROWS];

__device__ __forceinline__ u32 ex2h2(u32 s) {
    u32 r; asm("ex2.approx.f16x2 %0, %1;" : "=r"(r) : "r"(s)); return r;
}
__device__ __forceinline__ u32 prmt(u32 a, u32 b, u32 sel) {
    u32 r; asm("prmt.b32 %0, %1, %2, %3;" : "=r"(r) : "r"(a), "r"(b), "r"(sel)); return r;
}
__device__ __forceinline__ half2 h2(u32 v) { return *(half2*)&v; }
__device__ __forceinline__ u32 uu(half2 v) { return *(u32*)&v; }

// ---------------- Kernel 1: QKV projections, 4 lanes per row ----------------
__global__ __launch_bounds__(128) void proj_kernel(
    const float* __restrict__ x,
    const float* __restrict__ Kw, const float* __restrict__ Kb,
    const float* __restrict__ Qw, const float* __restrict__ Qb,
    const float* __restrict__ Vw, const float* __restrict__ Vb)
{
    __shared__ float sW[DIN * 24];   // per d: k[0..7] q[8..15] v[16..23]
    __shared__ float sB[24];
    int t = threadIdx.x;
    for (int i = t; i < DIN * DA; i += 128) {
        int d = i >> 3, a = i & 7;
        sW[d * 24 + a]      = Kw[i];
        sW[d * 24 + 8 + a]  = Qw[i];
        sW[d * 24 + 16 + a] = Vw[i];
    }
    if (t < DA) { sB[t] = Kb[t]; sB[8 + t] = Qb[t]; sB[16 + t] = Vb[t]; }
    __syncthreads();

    int gid  = blockIdx.x * 128 + t;
    int row  = gid >> 2;          // 4 lanes per row
    int part = gid & 3;           // dims [part*12, part*12+12)

    const float4* xp = (const float4*)(x + (size_t)row * DIN) + part * 3;

    float acc[24];
#pragma unroll
    for (int a = 0; a < 24; a++) acc[a] = 0.0f;
#pragma unroll
    for (int c = 0; c < 3; c++) {
        float4 x4 = xp[c];
        float xe[4] = {x4.x, x4.y, x4.z, x4.w};
#pragma unroll
        for (int e = 0; e < 4; e++) {
            float xv = xe[e];
            const float* w = &sW[(part * 12 + 4 * c + e) * 24];
#pragma unroll
            for (int a = 0; a < 24; a++) acc[a] = fmaf(xv, w[a], acc[a]);
        }
    }
    // reduce across the 4 lanes of this row
#pragma unroll
    for (int a = 0; a < 24; a++) {
        acc[a] += __shfl_xor_sync(0xFFFFFFFFu, acc[a], 1);
        acc[a] += __shfl_xor_sync(0xFFFFFFFFu, acc[a], 2);
    }
    if (part == 0) {
        const float SC = 1.4426950408889634f / 2.8284271247461903f;  // log2e/sqrt(8)
        half2 kh[4], qh[4], vh[4];
#pragma unroll
        for (int j = 0; j < 4; j++) {
            kh[j] = __floats2half2_rn((acc[2*j]   + sB[2*j])   * SC, (acc[2*j+1]  + sB[2*j+1]) * SC);
            qh[j] = __floats2half2_rn( acc[8+2*j] + sB[8+2*j],        acc[9+2*j]  + sB[9+2*j]);
            vh[j] = __floats2half2_rn( acc[16+2*j]+ sB[16+2*j],       acc[17+2*j] + sB[17+2*j]);
        }
        *(uint4*)(g_k + (size_t)row * DA) = *(uint4*)kh;
        *(uint4*)(g_q + (size_t)row * DA) = *(uint4*)qh;
        *(uint4*)(g_v + (size_t)row * DA) = *(uint4*)vh;
    }
}

// ---------------- Kernel 2: fp16x2 attention ----------------
__global__ __launch_bounds__(QTILE) void attn_kernel()
{
    // key-pair layout: sq[pair*8 + d] = half2{q_{2p}[d], q_{2p+1}[d]}
    __shared__ __align__(16) u32 sq[(CHUNK / 2) * 8];
    __shared__ __align__(16) u32 sv[(CHUNK / 2) * 8];

    int t = threadIdx.x;
    int row = blockIdx.x * QTILE + t;

    uint4 kraw = *(const uint4*)(g_k + (size_t)row * DA);
    half2 kk[DA];
    {
        half2* kp = (half2*)&kraw;
#pragma unroll
        for (int j = 0; j < 4; j++) {
            kk[2*j]   = __half2half2(__low2half(kp[j]));
            kk[2*j+1] = __half2half2(__high2half(kp[j]));
        }
    }

    float accF[DA];
#pragma unroll
    for (int a = 0; a < DA; a++) accF[a] = 0.0f;
    float ssumF = 0.0f;

    int kbase = blockIdx.y * (NROWS / KSPLIT);

    for (int c = 0; c < NCHUNKS; c++) {
        int kc = kbase + c * CHUNK;
        __syncthreads();
        {
            // threads 0-63 fill q pairs, 64-127 fill v pairs
            int pairIdx = t & 63;
            const __half* src = (t < 64) ? g_q : g_v;
            const uint4* sp = (const uint4*)(src + (size_t)(kc + 2 * pairIdx) * DA);
            uint4 r0 = sp[0], r1 = sp[1];   // rows 2p, 2p+1 (8 halves each)
            u32 o0 = prmt(r0.x, r1.x, 0x5410), o1 = prmt(r0.x, r1.x, 0x7632);
            u32 o2 = prmt(r0.y, r1.y, 0x5410), o3 = prmt(r0.y, r1.y, 0x7632);
            u32 o4 = prmt(r0.z, r1.z, 0x5410), o5 = prmt(r0.z, r1.z, 0x7632);
            u32 o6 = prmt(r0.w, r1.w, 0x5410), o7 = prmt(r0.w, r1.w, 0x7632);
            u32* dst = ((t < 64) ? sq : sv) + pairIdx * 8;
            ((uint4*)dst)[0] = make_uint4(o0, o1, o2, o3);
            ((uint4*)dst)[1] = make_uint4(o4, o5, o6, o7);
        }
        __syncthreads();

        half2 acc[DA];
#pragma unroll
        for (int a = 0; a < DA; a++) acc[a] = __floats2half2_rn(0.f, 0.f);
        half2 ssum = __floats2half2_rn(0.f, 0.f);

        const uint4* q4 = (const uint4*)sq;
        const uint4* v4 = (const uint4*)sv;
#pragma unroll 8
        for (int jp = 0; jp < CHUNK / 2; jp++) {
            uint4 qA = q4[2 * jp], qB = q4[2 * jp + 1];
            half2 s = __hmul2(kk[0], h2(qA.x));
            s = __hfma2(kk[1], h2(qA.y), s);
            s = __hfma2(kk[2], h2(qA.z), s);
            s = __hfma2(kk[3], h2(qA.w), s);
            s = __hfma2(kk[4], h2(qB.x), s);
            s = __hfma2(kk[5], h2(qB.y), s);
            s = __hfma2(kk[6], h2(qB.z), s);
            s = __hfma2(kk[7], h2(qB.w), s);
            half2 p = h2(ex2h2(uu(s)));
            ssum = __hadd2(ssum, p);
            uint4 vA = v4[2 * jp], vB = v4[2 * jp + 1];
            acc[0] = __hfma2(p, h2(vA.x), acc[0]);
            acc[1] = __hfma2(p, h2(vA.y), acc[1]);
            acc[2] = __hfma2(p, h2(vA.z), acc[2]);
            acc[3] = __hfma2(p, h2(vA.w), acc[3]);
            acc[4] = __hfma2(p, h2(vB.x), acc[4]);
            acc[5] = __hfma2(p, h2(vB.y), acc[5]);
            acc[6] = __hfma2(p, h2(vB.z), acc[6]);
            acc[7] = __hfma2(p, h2(vB.w), acc[7]);
        }

        // drain chunk accumulators to fp32
#pragma unroll
        for (int a = 0; a < DA; a++) {
            float2 f = __half22float2(acc[a]);
            accF[a] += f.x + f.y;
        }
        float2 fs = __half22float2(ssum);
        ssumF += fs.x + fs.y;
    }

    int o = blockIdx.y * NROWS + row;
    float4* ap = (float4*)(g_acc + (size_t)o * DA);
    ap[0] = make_float4(accF[0], accF[1], accF[2], accF[3]);
    ap[1] = make_float4(accF[4], accF[5], accF[6], accF[7]);
    g_sum[o] = ssumF;
}

// ---------------- Kernel 3: reduce partials + normalize + output proj + residual ----------------
__global__ __launch_bounds__(128) void final_kernel(
    const float* __restrict__ x,
    const float* __restrict__ Zw, const float* __restrict__ Zb,
    float* __restrict__ out)
{
    __shared__ float sZ[DA * DIN];
    __shared__ float sZb[DIN];
    int t = threadIdx.x;
    for (int i = t; i < DA * DIN; i += 128) sZ[i] = Zw[i];
    if (t < DIN) sZb[t] = Zb[t];
    __syncthreads();

    int row = blockIdx.x * 128 + t;

    float acc[DA];
#pragma unroll
    for (int a = 0; a < DA; a++) acc[a] = 0.0f;
    float ssum = 0.0f;
#pragma unroll
    for (int s = 0; s < KSPLIT; s++) {
        int o = s * NROWS + row;
        ssum += g_sum[o];
        const float4* ap = (const float4*)(g_acc + (size_t)o * DA);
        float4 a0 = ap[0], a1 = ap[1];
        acc[0] += a0.x; acc[1] += a0.y; acc[2] += a0.z; acc[3] += a0.w;
        acc[4] += a1.x; acc[5] += a1.y; acc[6] += a1.z; acc[7] += a1.w;
    }
    float inv = 1.0f / ssum;
    float z[DA];
#pragma unroll
    for (int a = 0; a < DA; a++) z[a] = acc[a] * inv;

    const float4* xp = (const float4*)(x + (size_t)row * DIN);
    float4* op = (float4*)(out + (size_t)row * DIN);
#pragma unroll
    for (int ch = 0; ch < DIN / 8; ch++) {
        float4 xa = xp[2 * ch], xb = xp[2 * ch + 1];
        float o8[8];
        o8[0] = xa.x + sZb[8 * ch + 0]; o8[1] = xa.y + sZb[8 * ch + 1];
        o8[2] = xa.z + sZb[8 * ch + 2]; o8[3] = xa.w + sZb[8 * ch + 3];
        o8[4] = xb.x + sZb[8 * ch + 4]; o8[5] = xb.y + sZb[8 * ch + 5];
        o8[6] = xb.z + sZb[8 * ch + 6]; o8[7] = xb.w + sZb[8 * ch + 7];
#pragma unroll
        for (int a = 0; a < DA; a++) {
            float za = z[a];
            const float* w = &sZ[a * DIN + 8 * ch];
#pragma unroll
            for (int e = 0; e < 8; e++) o8[e] = fmaf(za, w[e], o8[e]);
        }
        op[2 * ch]     = make_float4(o8[0], o8[1], o8[2], o8[3]);
        op[2 * ch + 1] = make_float4(o8[4], o8[5], o8[6], o8[7]);
    }
}

extern "C" void kernel_launch(void* const* d_in, const int* in_sizes, int n_in,
                              void* d_out, int out_size)
{
    (void)in_sizes; (void)n_in; (void)out_size;
    const float* x  = (const float*)d_in[0];
    const float* Kw = (const float*)d_in[1];
    const float* Kb = (const float*)d_in[2];
    const float* Qw = (const float*)d_in[3];
    const float* Qb = (const float*)d_in[4];
    const float* Vw = (const float*)d_in[5];
    const float* Vb = (const float*)d_in[6];
    const float* Zw = (const float*)d_in[7];
    const float* Zb = (const float*)d_in[8];
    float* out = (float*)d_out;

    proj_kernel<<<NROWS * 4 / 128, 128>>>(x, Kw, Kb, Qw, Qb, Vw, Vb);
    dim3 ga(NROWS / QTILE, KSPLIT);
    attn_kernel<<<ga, QTILE>>>();
    final_kernel<<<NROWS / 128, 128>>>(x, Zw, Zb, out);
}

// round 6
// speedup vs baseline: 1.3891x; 1.0367x over previous
#include <cuda_runtime.h>
#include <cuda_fp16.h>
#include <cstdint>

// Ultimus R6: HFMA2 attention with 2 q-rows/thread (LDS+MUFU amortized), 1-thread-per-
// output proj, KSPLIT=16. exp2 folded scale in Xk; fp16 chunk accumulators -> fp32.

#define NROWS 8192
#define DIN   48
#define DA    8
#define KSPLIT 16
#define CHUNK 128
#define NCHUNKS ((NROWS / KSPLIT) / CHUNK)   // 4

typedef unsigned int u32;

__device__ __align__(16) __half g_k[NROWS * DA];   // Xk * log2e/sqrt(8)
__device__ __align__(16) __half g_q[NROWS * DA];
__device__ __align__(16) __half g_v[NROWS * DA];
__device__ __align__(16) float g_acc[KSPLIT * NROWS * DA];
__device__ float g_sum[KSPLIT * NROWS];

__device__ __forceinline__ u32 ex2h2(u32 s) {
    u32 r; asm("ex2.approx.f16x2 %0, %1;" : "=r"(r) : "r"(s)); return r;
}
__device__ __forceinline__ u32 prmt(u32 a, u32 b, u32 sel) {
    u32 r; asm("prmt.b32 %0, %1, %2, %3;" : "=r"(r) : "r"(a), "r"(b), "r"(sel)); return r;
}
__device__ __forceinline__ half2 h2(u32 v) { return *(half2*)&v; }
__device__ __forceinline__ u32 uu(half2 v) { return *(u32*)&v; }

// ---------------- Kernel 1: proj, 1 thread per (row, output) ----------------
__global__ __launch_bounds__(256) void proj_kernel(
    const float* __restrict__ x,
    const float* __restrict__ Kw, const float* __restrict__ Kb,
    const float* __restrict__ Qw, const float* __restrict__ Qb,
    const float* __restrict__ Vw, const float* __restrict__ Vb)
{
    __shared__ float sWc[24 * DIN];   // column-major: sWc[a*48 + d]
    __shared__ float sBb[24];
    int t = threadIdx.x;
    for (int i = t; i < 24 * DIN; i += 256) {
        int a = i / DIN, d = i % DIN;
        const float* W = (a < 8) ? Kw : (a < 16) ? Qw : Vw;
        sWc[i] = W[d * DA + (a & 7)];
    }
    if (t < 24) sBb[t] = (t < 8) ? Kb[t] : (t < 16) ? Qb[t - 8] : Vb[t - 16];
    __syncthreads();

    int gid = blockIdx.x * 256 + t;
    int row = gid / 24;
    int a   = gid - row * 24;

    const float4* xp = (const float4*)(x + (size_t)row * DIN);
    const float4* wp = (const float4*)(sWc + a * DIN);

    float s0 = sBb[a], s1 = 0.f, s2 = 0.f, s3 = 0.f;
#pragma unroll
    for (int i = 0; i < DIN / 16; i++) {
        float4 xa = xp[4 * i + 0], wa = wp[4 * i + 0];
        float4 xb = xp[4 * i + 1], wb = wp[4 * i + 1];
        float4 xc = xp[4 * i + 2], wc = wp[4 * i + 2];
        float4 xd = xp[4 * i + 3], wd = wp[4 * i + 3];
        s0 = fmaf(xa.x, wa.x, s0); s0 = fmaf(xa.y, wa.y, s0);
        s0 = fmaf(xa.z, wa.z, s0); s0 = fmaf(xa.w, wa.w, s0);
        s1 = fmaf(xb.x, wb.x, s1); s1 = fmaf(xb.y, wb.y, s1);
        s1 = fmaf(xb.z, wb.z, s1); s1 = fmaf(xb.w, wb.w, s1);
        s2 = fmaf(xc.x, wc.x, s2); s2 = fmaf(xc.y, wc.y, s2);
        s2 = fmaf(xc.z, wc.z, s2); s2 = fmaf(xc.w, wc.w, s2);
        s3 = fmaf(xd.x, wd.x, s3); s3 = fmaf(xd.y, wd.y, s3);
        s3 = fmaf(xd.z, wd.z, s3); s3 = fmaf(xd.w, wd.w, s3);
    }
    float acc = (s0 + s1) + (s2 + s3);

    const float SC = 1.4426950408889634f / 2.8284271247461903f;  // log2e/sqrt(8)
    if (a < 8) {
        g_k[row * DA + a] = __float2half_rn(acc * SC);
    } else if (a < 16) {
        g_q[row * DA + (a - 8)] = __float2half_rn(acc);
    } else {
        g_v[row * DA + (a - 16)] = __float2half_rn(acc);
    }
}

// ---------------- Kernel 2: fp16x2 attention, 2 rows/thread ----------------
__global__ __launch_bounds__(64) void attn_kernel()
{
    // key-pair layout: sq[pair*8 + d] = half2{q_{2p}[d], q_{2p+1}[d]}
    __shared__ __align__(16) u32 sq[(CHUNK / 2) * 8];
    __shared__ __align__(16) u32 sv[(CHUNK / 2) * 8];

    int t = threadIdx.x;
    int r0 = blockIdx.x * 128 + t;
    int r1 = r0 + 64;

    half2 kk0[DA], kk1[DA];
    {
        uint4 kr0 = *(const uint4*)(g_k + (size_t)r0 * DA);
        uint4 kr1 = *(const uint4*)(g_k + (size_t)r1 * DA);
        half2* p0 = (half2*)&kr0;
        half2* p1 = (half2*)&kr1;
#pragma unroll
        for (int j = 0; j < 4; j++) {
            kk0[2*j]   = __half2half2(__low2half(p0[j]));
            kk0[2*j+1] = __half2half2(__high2half(p0[j]));
            kk1[2*j]   = __half2half2(__low2half(p1[j]));
            kk1[2*j+1] = __half2half2(__high2half(p1[j]));
        }
    }

    float accF0[DA], accF1[DA];
#pragma unroll
    for (int a = 0; a < DA; a++) { accF0[a] = 0.f; accF1[a] = 0.f; }
    float ssumF0 = 0.f, ssumF1 = 0.f;

    int kbase = blockIdx.y * (NROWS / KSPLIT);

    for (int c = 0; c < NCHUNKS; c++) {
        int kc = kbase + c * CHUNK;
        __syncthreads();
        {
            // thread t stages key pair (2t, 2t+1) for both q and v
            const uint4* qp = (const uint4*)(g_q + (size_t)(kc + 2 * t) * DA);
            uint4 q0 = qp[0], q1 = qp[1];
            ((uint4*)(sq + t * 8))[0] = make_uint4(prmt(q0.x, q1.x, 0x5410), prmt(q0.x, q1.x, 0x7632),
                                                  prmt(q0.y, q1.y, 0x5410), prmt(q0.y, q1.y, 0x7632));
            ((uint4*)(sq + t * 8))[1] = make_uint4(prmt(q0.z, q1.z, 0x5410), prmt(q0.z, q1.z, 0x7632),
                                                  prmt(q0.w, q1.w, 0x5410), prmt(q0.w, q1.w, 0x7632));
            const uint4* vp = (const uint4*)(g_v + (size_t)(kc + 2 * t) * DA);
            uint4 v0 = vp[0], v1 = vp[1];
            ((uint4*)(sv + t * 8))[0] = make_uint4(prmt(v0.x, v1.x, 0x5410), prmt(v0.x, v1.x, 0x7632),
                                                  prmt(v0.y, v1.y, 0x5410), prmt(v0.y, v1.y, 0x7632));
            ((uint4*)(sv + t * 8))[1] = make_uint4(prmt(v0.z, v1.z, 0x5410), prmt(v0.z, v1.z, 0x7632),
                                                  prmt(v0.w, v1.w, 0x5410), prmt(v0.w, v1.w, 0x7632));
        }
        __syncthreads();

        half2 acc0[DA], acc1[DA];
#pragma unroll
        for (int a = 0; a < DA; a++) { acc0[a] = __floats2half2_rn(0.f, 0.f); acc1[a] = acc0[a]; }
        half2 ssum0 = __floats2half2_rn(0.f, 0.f), ssum1 = ssum0;

        const uint4* q4 = (const uint4*)sq;
        const uint4* v4 = (const uint4*)sv;
#pragma unroll 4
        for (int jp = 0; jp < CHUNK / 2; jp++) {
            uint4 qA = q4[2 * jp], qB = q4[2 * jp + 1];
            half2 s0 = __hmul2(kk0[0], h2(qA.x));
            half2 s1 = __hmul2(kk1[0], h2(qA.x));
            s0 = __hfma2(kk0[1], h2(qA.y), s0);  s1 = __hfma2(kk1[1], h2(qA.y), s1);
            s0 = __hfma2(kk0[2], h2(qA.z), s0);  s1 = __hfma2(kk1[2], h2(qA.z), s1);
            s0 = __hfma2(kk0[3], h2(qA.w), s0);  s1 = __hfma2(kk1[3], h2(qA.w), s1);
            s0 = __hfma2(kk0[4], h2(qB.x), s0);  s1 = __hfma2(kk1[4], h2(qB.x), s1);
            s0 = __hfma2(kk0[5], h2(qB.y), s0);  s1 = __hfma2(kk1[5], h2(qB.y), s1);
            s0 = __hfma2(kk0[6], h2(qB.z), s0);  s1 = __hfma2(kk1[6], h2(qB.z), s1);
            s0 = __hfma2(kk0[7], h2(qB.w), s0);  s1 = __hfma2(kk1[7], h2(qB.w), s1);
            half2 p0 = h2(ex2h2(uu(s0)));
            half2 p1 = h2(ex2h2(uu(s1)));
            ssum0 = __hadd2(ssum0, p0);
            ssum1 = __hadd2(ssum1, p1);
            uint4 vA = v4[2 * jp], vB = v4[2 * jp + 1];
            acc0[0] = __hfma2(p0, h2(vA.x), acc0[0]);  acc1[0] = __hfma2(p1, h2(vA.x), acc1[0]);
            acc0[1] = __hfma2(p0, h2(vA.y), acc0[1]);  acc1[1] = __hfma2(p1, h2(vA.y), acc1[1]);
            acc0[2] = __hfma2(p0, h2(vA.z), acc0[2]);  acc1[2] = __hfma2(p1, h2(vA.z), acc1[2]);
            acc0[3] = __hfma2(p0, h2(vA.w), acc0[3]);  acc1[3] = __hfma2(p1, h2(vA.w), acc1[3]);
            acc0[4] = __hfma2(p0, h2(vB.x), acc0[4]);  acc1[4] = __hfma2(p1, h2(vB.x), acc1[4]);
            acc0[5] = __hfma2(p0, h2(vB.y), acc0[5]);  acc1[5] = __hfma2(p1, h2(vB.y), acc1[5]);
            acc0[6] = __hfma2(p0, h2(vB.z), acc0[6]);  acc1[6] = __hfma2(p1, h2(vB.z), acc1[6]);
            acc0[7] = __hfma2(p0, h2(vB.w), acc0[7]);  acc1[7] = __hfma2(p1, h2(vB.w), acc1[7]);
        }

#pragma unroll
        for (int a = 0; a < DA; a++) {
            float2 f0 = __half22float2(acc0[a]);
            float2 f1 = __half22float2(acc1[a]);
            accF0[a] += f0.x + f0.y;
            accF1[a] += f1.x + f1.y;
        }
        float2 fs0 = __half22float2(ssum0);
        float2 fs1 = __half22float2(ssum1);
        ssumF0 += fs0.x + fs0.y;
        ssumF1 += fs1.x + fs1.y;
    }

    int o0 = blockIdx.y * NROWS + r0;
    int o1 = blockIdx.y * NROWS + r1;
    float4* ap0 = (float4*)(g_acc + (size_t)o0 * DA);
    float4* ap1 = (float4*)(g_acc + (size_t)o1 * DA);
    ap0[0] = make_float4(accF0[0], accF0[1], accF0[2], accF0[3]);
    ap0[1] = make_float4(accF0[4], accF0[5], accF0[6], accF0[7]);
    ap1[0] = make_float4(accF1[0], accF1[1], accF1[2], accF1[3]);
    ap1[1] = make_float4(accF1[4], accF1[5], accF1[6], accF1[7]);
    g_sum[o0] = ssumF0;
    g_sum[o1] = ssumF1;
}

// ---------------- Kernel 3: reduce partials + normalize + output proj + residual ----------------
__global__ __launch_bounds__(128) void final_kernel(
    const float* __restrict__ x,
    const float* __restrict__ Zw, const float* __restrict__ Zb,
    float* __restrict__ out)
{
    __shared__ float sZ[DA * DIN];
    __shared__ float sZb[DIN];
    int t = threadIdx.x;
    for (int i = t; i < DA * DIN; i += 128) sZ[i] = Zw[i];
    if (t < DIN) sZb[t] = Zb[t];
    __syncthreads();

    int row = blockIdx.x * 128 + t;

    float acc[DA];
#pragma unroll
    for (int a = 0; a < DA; a++) acc[a] = 0.0f;
    float ssum = 0.0f;
#pragma unroll
    for (int s = 0; s < KSPLIT; s++) {
        int o = s * NROWS + row;
        ssum += g_sum[o];
        const float4* ap = (const float4*)(g_acc + (size_t)o * DA);
        float4 a0 = ap[0], a1 = ap[1];
        acc[0] += a0.x; acc[1] += a0.y; acc[2] += a0.z; acc[3] += a0.w;
        acc[4] += a1.x; acc[5] += a1.y; acc[6] += a1.z; acc[7] += a1.w;
    }
    float inv = 1.0f / ssum;
    float z[DA];
#pragma unroll
    for (int a = 0; a < DA; a++) z[a] = acc[a] * inv;

    const float4* xp = (const float4*)(x + (size_t)row * DIN);
    float4* op = (float4*)(out + (size_t)row * DIN);
#pragma unroll
    for (int ch = 0; ch < DIN / 8; ch++) {
        float4 xa = xp[2 * ch], xb = xp[2 * ch + 1];
        float o8[8];
        o8[0] = xa.x + sZb[8 * ch + 0]; o8[1] = xa.y + sZb[8 * ch + 1];
        o8[2] = xa.z + sZb[8 * ch + 2]; o8[3] = xa.w + sZb[8 * ch + 3];
        o8[4] = xb.x + sZb[8 * ch + 4]; o8[5] = xb.y + sZb[8 * ch + 5];
        o8[6] = xb.z + sZb[8 * ch + 6]; o8[7] = xb.w + sZb[8 * ch + 7];
#pragma unroll
        for (int a = 0; a < DA; a++) {
            float za = z[a];
            const float* w = &sZ[a * DIN + 8 * ch];
#pragma unroll
            for (int e = 0; e < 8; e++) o8[e] = fmaf(za, w[e], o8[e]);
        }
        op[2 * ch]     = make_float4(o8[0], o8[1], o8[2], o8[3]);
        op[2 * ch + 1] = make_float4(o8[4], o8[5], o8[6], o8[7]);
    }
}

extern "C" void kernel_launch(void* const* d_in, const int* in_sizes, int n_in,
                              void* d_out, int out_size)
{
    (void)in_sizes; (void)n_in; (void)out_size;
    const float* x  = (const float*)d_in[0];
    const float* Kw = (const float*)d_in[1];
    const float* Kb = (const float*)d_in[2];
    const float* Qw = (const float*)d_in[3];
    const float* Qb = (const float*)d_in[4];
    const float* Vw = (const float*)d_in[5];
    const float* Vb = (const float*)d_in[6];
    const float* Zw = (const float*)d_in[7];
    const float* Zb = (const float*)d_in[8];
    float* out = (float*)d_out;

    proj_kernel<<<(NROWS * 24) / 256, 256>>>(x, Kw, Kb, Qw, Qb, Vw, Vb);
    dim3 ga(NROWS / 128, KSPLIT);
    attn_kernel<<<ga, 64>>>();
    final_kernel<<<NROWS / 128, 128>>>(x, Zw, Zb, out);
}

// round 7
// speedup vs baseline: 1.7398x; 1.2524x over previous
#include <cuda_runtime.h>
#include <cuda_fp16.h>
#include <cstdint>

// Ultimus R7: HFMA2 attention, KSPLIT=32 (one 256-key smem stage per block, 6.9 warps/SMSP),
// R3-shape proj (best measured) with fp16 out, final with 4 threads/row.

#define NROWS 8192
#define DIN   48
#define DA    8
#define KSPLIT 32
#define SPLIT 256                 // keys per split == keys per block (staged once)
#define NPAIRS (SPLIT / 2)        // 128

typedef unsigned int u32;

__device__ __align__(16) __half g_k[NROWS * DA];   // Xk * log2e/sqrt(8)
__device__ __align__(16) __half g_q[NROWS * DA];
__device__ __align__(16) __half g_v[NROWS * DA];
__device__ __align__(16) float g_acc[KSPLIT * NROWS * DA];
__device__ float g_sum[KSPLIT * NROWS];

__device__ __forceinline__ u32 ex2h2(u32 s) {
    u32 r; asm("ex2.approx.f16x2 %0, %1;" : "=r"(r) : "r"(s)); return r;
}
__device__ __forceinline__ u32 prmt(u32 a, u32 b, u32 sel) {
    u32 r; asm("prmt.b32 %0, %1, %2, %3;" : "=r"(r) : "r"(a), "r"(b), "r"(sel)); return r;
}
__device__ __forceinline__ half2 h2(u32 v) { return *(half2*)&v; }
__device__ __forceinline__ u32 uu(half2 v) { return *(u32*)&v; }

// ---------------- Kernel 1: proj (R3 shape: row/thread, x in regs, grid.y = matrix) ----------------
__global__ __launch_bounds__(128) void proj_kernel(
    const float* __restrict__ x,
    const float* __restrict__ Kw, const float* __restrict__ Kb,
    const float* __restrict__ Qw, const float* __restrict__ Qb,
    const float* __restrict__ Vw, const float* __restrict__ Vb)
{
    __shared__ float sW[DIN * DA];
    __shared__ float sB[DA];
    int t = threadIdx.x;
    int which = blockIdx.y;
    const float* W = (which == 0) ? Kw : (which == 1) ? Qw : Vw;
    const float* B = (which == 0) ? Kb : (which == 1) ? Qb : Vb;
    for (int i = t; i < DIN * DA; i += 128) sW[i] = W[i];
    if (t < DA) sB[t] = B[t];
    __syncthreads();

    float scale = (which == 0) ? (1.4426950408889634f / 2.8284271247461903f) : 1.0f;

    int row = blockIdx.x * 128 + t;
    const float4* xp = (const float4*)(x + (size_t)row * DIN);

    float acc[DA];
#pragma unroll
    for (int a = 0; a < DA; a++) acc[a] = sB[a];

#pragma unroll
    for (int c = 0; c < DIN / 4; c++) {
        float4 x4 = xp[c];
        float xe[4] = {x4.x, x4.y, x4.z, x4.w};
#pragma unroll
        for (int e = 0; e < 4; e++) {
            float xv = xe[e];
            const float* w = &sW[(4 * c + e) * DA];
#pragma unroll
            for (int a = 0; a < DA; a++) acc[a] = fmaf(xv, w[a], acc[a]);
        }
    }

    __half* dst = ((which == 0) ? g_k : (which == 1) ? g_q : g_v) + (size_t)row * DA;
    half2 h[4];
#pragma unroll
    for (int j = 0; j < 4; j++)
        h[j] = __floats2half2_rn(acc[2 * j] * scale, acc[2 * j + 1] * scale);
    *(uint4*)dst = *(uint4*)h;
}

// ---------------- Kernel 2: fp16x2 attention, one staged 256-key split ----------------
__global__ __launch_bounds__(128) void attn_kernel()
{
    // key-pair layout: sq[pair*8 + d] = half2{q_{2p}[d], q_{2p+1}[d]}
    __shared__ __align__(16) u32 sq[NPAIRS * 8];
    __shared__ __align__(16) u32 sv[NPAIRS * 8];

    int t = threadIdx.x;
    int r0 = blockIdx.x * 256 + t;
    int r1 = r0 + 128;
    int kbase = blockIdx.y * SPLIT;

    // stage the whole split: thread t stages key pair (kbase+2t, kbase+2t+1)
    {
        const uint4* qp = (const uint4*)(g_q + (size_t)(kbase + 2 * t) * DA);
        uint4 q0 = qp[0], q1 = qp[1];
        ((uint4*)(sq + t * 8))[0] = make_uint4(prmt(q0.x, q1.x, 0x5410), prmt(q0.x, q1.x, 0x7632),
                                              prmt(q0.y, q1.y, 0x5410), prmt(q0.y, q1.y, 0x7632));
        ((uint4*)(sq + t * 8))[1] = make_uint4(prmt(q0.z, q1.z, 0x5410), prmt(q0.z, q1.z, 0x7632),
                                              prmt(q0.w, q1.w, 0x5410), prmt(q0.w, q1.w, 0x7632));
        const uint4* vp = (const uint4*)(g_v + (size_t)(kbase + 2 * t) * DA);
        uint4 v0 = vp[0], v1 = vp[1];
        ((uint4*)(sv + t * 8))[0] = make_uint4(prmt(v0.x, v1.x, 0x5410), prmt(v0.x, v1.x, 0x7632),
                                              prmt(v0.y, v1.y, 0x5410), prmt(v0.y, v1.y, 0x7632));
        ((uint4*)(sv + t * 8))[1] = make_uint4(prmt(v0.z, v1.z, 0x5410), prmt(v0.z, v1.z, 0x7632),
                                              prmt(v0.w, v1.w, 0x5410), prmt(v0.w, v1.w, 0x7632));
    }

    half2 kk0[DA], kk1[DA];
    {
        uint4 kr0 = *(const uint4*)(g_k + (size_t)r0 * DA);
        uint4 kr1 = *(const uint4*)(g_k + (size_t)r1 * DA);
        half2* p0 = (half2*)&kr0;
        half2* p1 = (half2*)&kr1;
#pragma unroll
        for (int j = 0; j < 4; j++) {
            kk0[2*j]   = __half2half2(__low2half(p0[j]));
            kk0[2*j+1] = __half2half2(__high2half(p0[j]));
            kk1[2*j]   = __half2half2(__low2half(p1[j]));
            kk1[2*j+1] = __half2half2(__high2half(p1[j]));
        }
    }

    float accF0[DA], accF1[DA];
#pragma unroll
    for (int a = 0; a < DA; a++) { accF0[a] = 0.f; accF1[a] = 0.f; }
    float ssumF0 = 0.f, ssumF1 = 0.f;

    __syncthreads();

    const uint4* q4 = (const uint4*)sq;
    const uint4* v4 = (const uint4*)sv;

#pragma unroll
    for (int hlf = 0; hlf < 2; hlf++) {
        half2 acc0[DA], acc1[DA];
#pragma unroll
        for (int a = 0; a < DA; a++) { acc0[a] = __floats2half2_rn(0.f, 0.f); acc1[a] = acc0[a]; }
        half2 ssum0 = __floats2half2_rn(0.f, 0.f), ssum1 = ssum0;

#pragma unroll 4
        for (int jp = hlf * (NPAIRS / 2); jp < (hlf + 1) * (NPAIRS / 2); jp++) {
            uint4 qA = q4[2 * jp], qB = q4[2 * jp + 1];
            half2 s0 = __hmul2(kk0[0], h2(qA.x));
            half2 s1 = __hmul2(kk1[0], h2(qA.x));
            s0 = __hfma2(kk0[1], h2(qA.y), s0);  s1 = __hfma2(kk1[1], h2(qA.y), s1);
            s0 = __hfma2(kk0[2], h2(qA.z), s0);  s1 = __hfma2(kk1[2], h2(qA.z), s1);
            s0 = __hfma2(kk0[3], h2(qA.w), s0);  s1 = __hfma2(kk1[3], h2(qA.w), s1);
            s0 = __hfma2(kk0[4], h2(qB.x), s0);  s1 = __hfma2(kk1[4], h2(qB.x), s1);
            s0 = __hfma2(kk0[5], h2(qB.y), s0);  s1 = __hfma2(kk1[5], h2(qB.y), s1);
            s0 = __hfma2(kk0[6], h2(qB.z), s0);  s1 = __hfma2(kk1[6], h2(qB.z), s1);
            s0 = __hfma2(kk0[7], h2(qB.w), s0);  s1 = __hfma2(kk1[7], h2(qB.w), s1);
            half2 p0 = h2(ex2h2(uu(s0)));
            half2 p1 = h2(ex2h2(uu(s1)));
            ssum0 = __hadd2(ssum0, p0);
            ssum1 = __hadd2(ssum1, p1);
            uint4 vA = v4[2 * jp], vB = v4[2 * jp + 1];
            acc0[0] = __hfma2(p0, h2(vA.x), acc0[0]);  acc1[0] = __hfma2(p1, h2(vA.x), acc1[0]);
            acc0[1] = __hfma2(p0, h2(vA.y), acc0[1]);  acc1[1] = __hfma2(p1, h2(vA.y), acc1[1]);
            acc0[2] = __hfma2(p0, h2(vA.z), acc0[2]);  acc1[2] = __hfma2(p1, h2(vA.z), acc1[2]);
            acc0[3] = __hfma2(p0, h2(vA.w), acc0[3]);  acc1[3] = __hfma2(p1, h2(vA.w), acc1[3]);
            acc0[4] = __hfma2(p0, h2(vB.x), acc0[4]);  acc1[4] = __hfma2(p1, h2(vB.x), acc1[4]);
            acc0[5] = __hfma2(p0, h2(vB.y), acc0[5]);  acc1[5] = __hfma2(p1, h2(vB.y), acc1[5]);
            acc0[6] = __hfma2(p0, h2(vB.z), acc0[6]);  acc1[6] = __hfma2(p1, h2(vB.z), acc1[6]);
            acc0[7] = __hfma2(p0, h2(vB.w), acc0[7]);  acc1[7] = __hfma2(p1, h2(vB.w), acc1[7]);
        }

#pragma unroll
        for (int a = 0; a < DA; a++) {
            float2 f0 = __half22float2(acc0[a]);
            float2 f1 = __half22float2(acc1[a]);
            accF0[a] += f0.x + f0.y;
            accF1[a] += f1.x + f1.y;
        }
        float2 fs0 = __half22float2(ssum0);
        float2 fs1 = __half22float2(ssum1);
        ssumF0 += fs0.x + fs0.y;
        ssumF1 += fs1.x + fs1.y;
    }

    int o0 = blockIdx.y * NROWS + r0;
    int o1 = blockIdx.y * NROWS + r1;
    float4* ap0 = (float4*)(g_acc + (size_t)o0 * DA);
    float4* ap1 = (float4*)(g_acc + (size_t)o1 * DA);
    ap0[0] = make_float4(accF0[0], accF0[1], accF0[2], accF0[3]);
    ap0[1] = make_float4(accF0[4], accF0[5], accF0[6], accF0[7]);
    ap1[0] = make_float4(accF1[0], accF1[1], accF1[2], accF1[3]);
    ap1[1] = make_float4(accF1[4], accF1[5], accF1[6], accF1[7]);
    g_sum[o0] = ssumF0;
    g_sum[o1] = ssumF1;
}

// ---------------- Kernel 3: final, 4 threads per row ----------------
__global__ __launch_bounds__(128) void final_kernel(
    const float* __restrict__ x,
    const float* __restrict__ Zw, const float* __restrict__ Zb,
    float* __restrict__ out)
{
    __shared__ float sZ[DA * DIN];
    __shared__ float sZb[DIN];
    int t = threadIdx.x;
    for (int i = t; i < DA * DIN; i += 128) sZ[i] = Zw[i];
    if (t < DIN) sZb[t] = Zb[t];
    __syncthreads();

    int gid  = blockIdx.x * 128 + t;
    int row  = gid >> 2;
    int part = gid & 3;

    // each of 4 threads sums 8 splits
    float acc[DA];
#pragma unroll
    for (int a = 0; a < DA; a++) acc[a] = 0.0f;
    float ssum = 0.0f;
#pragma unroll
    for (int i = 0; i < KSPLIT / 4; i++) {
        int o = (part * (KSPLIT / 4) + i) * NROWS + row;
        ssum += g_sum[o];
        const float4* ap = (const float4*)(g_acc + (size_t)o * DA);
        float4 a0 = ap[0], a1 = ap[1];
        acc[0] += a0.x; acc[1] += a0.y; acc[2] += a0.z; acc[3] += a0.w;
        acc[4] += a1.x; acc[5] += a1.y; acc[6] += a1.z; acc[7] += a1.w;
    }
    // combine the 4 partial sums (threads 4r..4r+3 are a contiguous quad)
#pragma unroll
    for (int a = 0; a < DA; a++) {
        acc[a] += __shfl_xor_sync(0xFFFFFFFFu, acc[a], 1);
        acc[a] += __shfl_xor_sync(0xFFFFFFFFu, acc[a], 2);
    }
    ssum += __shfl_xor_sync(0xFFFFFFFFu, ssum, 1);
    ssum += __shfl_xor_sync(0xFFFFFFFFu, ssum, 2);

    float inv = 1.0f / ssum;
    float z[DA];
#pragma unroll
    for (int a = 0; a < DA; a++) z[a] = acc[a] * inv;

    // each thread writes 12 of the 48 output dims
    const float4* xp = (const float4*)(x + (size_t)row * DIN) + part * 3;
    float4* op = (float4*)(out + (size_t)row * DIN) + part * 3;
#pragma unroll
    for (int c = 0; c < 3; c++) {
        int d0 = part * 12 + 4 * c;
        float4 xv = xp[c];
        float o4[4] = {xv.x + sZb[d0], xv.y + sZb[d0 + 1], xv.z + sZb[d0 + 2], xv.w + sZb[d0 + 3]};
#pragma unroll
        for (int a = 0; a < DA; a++) {
            float za = z[a];
            const float* w = &sZ[a * DIN + d0];
            o4[0] = fmaf(za, w[0], o4[0]);
            o4[1] = fmaf(za, w[1], o4[1]);
            o4[2] = fmaf(za, w[2], o4[2]);
            o4[3] = fmaf(za, w[3], o4[3]);
        }
        op[c] = make_float4(o4[0], o4[1], o4[2], o4[3]);
    }
}

extern "C" void kernel_launch(void* const* d_in, const int* in_sizes, int n_in,
                              void* d_out, int out_size)
{
    (void)in_sizes; (void)n_in; (void)out_size;
    const float* x  = (const float*)d_in[0];
    const float* Kw = (const float*)d_in[1];
    const float* Kb = (const float*)d_in[2];
    const float* Qw = (const float*)d_in[3];
    const float* Qb = (const float*)d_in[4];
    const float* Vw = (const float*)d_in[5];
    const float* Vb = (const float*)d_in[6];
    const float* Zw = (const float*)d_in[7];
    const float* Zb = (const float*)d_in[8];
    float* out = (float*)d_out;

    dim3 gp(NROWS / 128, 3);
    proj_kernel<<<gp, 128>>>(x, Kw, Kb, Qw, Qb, Vw, Vb);
    dim3 ga(NROWS / 256, KSPLIT);
    attn_kernel<<<ga, 128>>>();
    final_kernel<<<(NROWS * 4) / 128, 128>>>(x, Zw, Zb, out);
}

// round 8
// speedup vs baseline: 1.8077x; 1.0390x over previous
#include <cuda_runtime.h>
#include <cuda_fp16.h>
#include <cstdint>

// Ultimus R8: attn unchanged (at HFMA2 roofline). proj reworked: 4 threads per
// (row, matrix), 12-dim slices, quad shfl reduce -> 5.2 warps/SMSP latency hiding.

#define NROWS 8192
#define DIN   48
#define DA    8
#define KSPLIT 32
#define SPLIT 256
#define NPAIRS (SPLIT / 2)

typedef unsigned int u32;

__device__ __align__(16) __half g_k[NROWS * DA];   // Xk * log2e/sqrt(8)
__device__ __align__(16) __half g_q[NROWS * DA];
__device__ __align__(16) __half g_v[NROWS * DA];
__device__ __align__(16) float g_acc[KSPLIT * NROWS * DA];
__device__ float g_sum[KSPLIT * NROWS];

__device__ __forceinline__ u32 ex2h2(u32 s) {
    u32 r; asm("ex2.approx.f16x2 %0, %1;" : "=r"(r) : "r"(s)); return r;
}
__device__ __forceinline__ u32 prmt(u32 a, u32 b, u32 sel) {
    u32 r; asm("prmt.b32 %0, %1, %2, %3;" : "=r"(r) : "r"(a), "r"(b), "r"(sel)); return r;
}
__device__ __forceinline__ half2 h2(u32 v) { return *(half2*)&v; }
__device__ __forceinline__ u32 uu(half2 v) { return *(u32*)&v; }

// ---------------- Kernel 1: proj, 4 threads per (row, matrix) ----------------
__global__ __launch_bounds__(256) void proj_kernel(
    const float* __restrict__ x,
    const float* __restrict__ Kw, const float* __restrict__ Kb,
    const float* __restrict__ Qw, const float* __restrict__ Qb,
    const float* __restrict__ Vw, const float* __restrict__ Vb)
{
    __shared__ float sWc[DA * DIN];   // column-major: sWc[a*48 + d]
    __shared__ float sB[DA];
    int t = threadIdx.x;
    int which = blockIdx.y;
    const float* W = (which == 0) ? Kw : (which == 1) ? Qw : Vw;
    const float* B = (which == 0) ? Kb : (which == 1) ? Qb : Vb;
    for (int i = t; i < DA * DIN; i += 256) {
        int a = i / DIN, d = i - a * DIN;
        sWc[i] = W[d * DA + a];
    }
    if (t < DA) sB[t] = B[t];
    __syncthreads();

    float scale = (which == 0) ? (1.4426950408889634f / 2.8284271247461903f) : 1.0f;

    int row  = blockIdx.x * 64 + (t >> 2);
    int part = t & 3;

    const float4* xp = (const float4*)(x + (size_t)row * DIN) + part * 3;
    float4 x0 = xp[0], x1 = xp[1], x2 = xp[2];

    float acc[DA];
#pragma unroll
    for (int a = 0; a < DA; a++) {
        const float4* wp = (const float4*)(sWc + a * DIN + part * 12);
        float4 w0 = wp[0], w1 = wp[1], w2 = wp[2];
        float s0 = x0.x * w0.x;
        s0 = fmaf(x0.y, w0.y, s0);
        s0 = fmaf(x0.z, w0.z, s0);
        s0 = fmaf(x0.w, w0.w, s0);
        float s1 = x1.x * w1.x;
        s1 = fmaf(x1.y, w1.y, s1);
        s1 = fmaf(x1.z, w1.z, s1);
        s1 = fmaf(x1.w, w1.w, s1);
        float s2 = x2.x * w2.x;
        s2 = fmaf(x2.y, w2.y, s2);
        s2 = fmaf(x2.z, w2.z, s2);
        s2 = fmaf(x2.w, w2.w, s2);
        acc[a] = s0 + s1 + s2;
    }

    // reduce the quad (lanes 4r..4r+3)
#pragma unroll
    for (int a = 0; a < DA; a++) {
        acc[a] += __shfl_xor_sync(0xFFFFFFFFu, acc[a], 1);
        acc[a] += __shfl_xor_sync(0xFFFFFFFFu, acc[a], 2);
    }

    if (part == 0) {
        __half* dst = ((which == 0) ? g_k : (which == 1) ? g_q : g_v) + (size_t)row * DA;
        half2 h[4];
#pragma unroll
        for (int j = 0; j < 4; j++)
            h[j] = __floats2half2_rn((acc[2 * j] + sB[2 * j]) * scale,
                                     (acc[2 * j + 1] + sB[2 * j + 1]) * scale);
        *(uint4*)dst = *(uint4*)h;
    }
}

// ---------------- Kernel 2: fp16x2 attention, one staged 256-key split ----------------
__global__ __launch_bounds__(128) void attn_kernel()
{
    __shared__ __align__(16) u32 sq[NPAIRS * 8];
    __shared__ __align__(16) u32 sv[NPAIRS * 8];

    int t = threadIdx.x;
    int r0 = blockIdx.x * 256 + t;
    int r1 = r0 + 128;
    int kbase = blockIdx.y * SPLIT;

    {
        const uint4* qp = (const uint4*)(g_q + (size_t)(kbase + 2 * t) * DA);
        uint4 q0 = qp[0], q1 = qp[1];
        ((uint4*)(sq + t * 8))[0] = make_uint4(prmt(q0.x, q1.x, 0x5410), prmt(q0.x, q1.x, 0x7632),
                                              prmt(q0.y, q1.y, 0x5410), prmt(q0.y, q1.y, 0x7632));
        ((uint4*)(sq + t * 8))[1] = make_uint4(prmt(q0.z, q1.z, 0x5410), prmt(q0.z, q1.z, 0x7632),
                                              prmt(q0.w, q1.w, 0x5410), prmt(q0.w, q1.w, 0x7632));
        const uint4* vp = (const uint4*)(g_v + (size_t)(kbase + 2 * t) * DA);
        uint4 v0 = vp[0], v1 = vp[1];
        ((uint4*)(sv + t * 8))[0] = make_uint4(prmt(v0.x, v1.x, 0x5410), prmt(v0.x, v1.x, 0x7632),
                                              prmt(v0.y, v1.y, 0x5410), prmt(v0.y, v1.y, 0x7632));
        ((uint4*)(sv + t * 8))[1] = make_uint4(prmt(v0.z, v1.z, 0x5410), prmt(v0.z, v1.z, 0x7632),
                                              prmt(v0.w, v1.w, 0x5410), prmt(v0.w, v1.w, 0x7632));
    }

    half2 kk0[DA], kk1[DA];
    {
        uint4 kr0 = *(const uint4*)(g_k + (size_t)r0 * DA);
        uint4 kr1 = *(const uint4*)(g_k + (size_t)r1 * DA);
        half2* p0 = (half2*)&kr0;
        half2* p1 = (half2*)&kr1;
#pragma unroll
        for (int j = 0; j < 4; j++) {
            kk0[2*j]   = __half2half2(__low2half(p0[j]));
            kk0[2*j+1] = __half2half2(__high2half(p0[j]));
            kk1[2*j]   = __half2half2(__low2half(p1[j]));
            kk1[2*j+1] = __half2half2(__high2half(p1[j]));
        }
    }

    float accF0[DA], accF1[DA];
#pragma unroll
    for (int a = 0; a < DA; a++) { accF0[a] = 0.f; accF1[a] = 0.f; }
    float ssumF0 = 0.f, ssumF1 = 0.f;

    __syncthreads();

    const uint4* q4 = (const uint4*)sq;
    const uint4* v4 = (const uint4*)sv;

#pragma unroll
    for (int hlf = 0; hlf < 2; hlf++) {
        half2 acc0[DA], acc1[DA];
#pragma unroll
        for (int a = 0; a < DA; a++) { acc0[a] = __floats2half2_rn(0.f, 0.f); acc1[a] = acc0[a]; }
        half2 ssum0 = __floats2half2_rn(0.f, 0.f), ssum1 = ssum0;

#pragma unroll 4
        for (int jp = hlf * (NPAIRS / 2); jp < (hlf + 1) * (NPAIRS / 2); jp++) {
            uint4 qA = q4[2 * jp], qB = q4[2 * jp + 1];
            half2 s0 = __hmul2(kk0[0], h2(qA.x));
            half2 s1 = __hmul2(kk1[0], h2(qA.x));
            s0 = __hfma2(kk0[1], h2(qA.y), s0);  s1 = __hfma2(kk1[1], h2(qA.y), s1);
            s0 = __hfma2(kk0[2], h2(qA.z), s0);  s1 = __hfma2(kk1[2], h2(qA.z), s1);
            s0 = __hfma2(kk0[3], h2(qA.w), s0);  s1 = __hfma2(kk1[3], h2(qA.w), s1);
            s0 = __hfma2(kk0[4], h2(qB.x), s0);  s1 = __hfma2(kk1[4], h2(qB.x), s1);
            s0 = __hfma2(kk0[5], h2(qB.y), s0);  s1 = __hfma2(kk1[5], h2(qB.y), s1);
            s0 = __hfma2(kk0[6], h2(qB.z), s0);  s1 = __hfma2(kk1[6], h2(qB.z), s1);
            s0 = __hfma2(kk0[7], h2(qB.w), s0);  s1 = __hfma2(kk1[7], h2(qB.w), s1);
            half2 p0 = h2(ex2h2(uu(s0)));
            half2 p1 = h2(ex2h2(uu(s1)));
            ssum0 = __hadd2(ssum0, p0);
            ssum1 = __hadd2(ssum1, p1);
            uint4 vA = v4[2 * jp], vB = v4[2 * jp + 1];
            acc0[0] = __hfma2(p0, h2(vA.x), acc0[0]);  acc1[0] = __hfma2(p1, h2(vA.x), acc1[0]);
            acc0[1] = __hfma2(p0, h2(vA.y), acc0[1]);  acc1[1] = __hfma2(p1, h2(vA.y), acc1[1]);
            acc0[2] = __hfma2(p0, h2(vA.z), acc0[2]);  acc1[2] = __hfma2(p1, h2(vA.z), acc1[2]);
            acc0[3] = __hfma2(p0, h2(vA.w), acc0[3]);  acc1[3] = __hfma2(p1, h2(vA.w), acc1[3]);
            acc0[4] = __hfma2(p0, h2(vB.x), acc0[4]);  acc1[4] = __hfma2(p1, h2(vB.x), acc1[4]);
            acc0[5] = __hfma2(p0, h2(vB.y), acc0[5]);  acc1[5] = __hfma2(p1, h2(vB.y), acc1[5]);
            acc0[6] = __hfma2(p0, h2(vB.z), acc0[6]);  acc1[6] = __hfma2(p1, h2(vB.z), acc1[6]);
            acc0[7] = __hfma2(p0, h2(vB.w), acc0[7]);  acc1[7] = __hfma2(p1, h2(vB.w), acc1[7]);
        }

#pragma unroll
        for (int a = 0; a < DA; a++) {
            float2 f0 = __half22float2(acc0[a]);
            float2 f1 = __half22float2(acc1[a]);
            accF0[a] += f0.x + f0.y;
            accF1[a] += f1.x + f1.y;
        }
        float2 fs0 = __half22float2(ssum0);
        float2 fs1 = __half22float2(ssum1);
        ssumF0 += fs0.x + fs0.y;
        ssumF1 += fs1.x + fs1.y;
    }

    int o0 = blockIdx.y * NROWS + r0;
    int o1 = blockIdx.y * NROWS + r1;
    float4* ap0 = (float4*)(g_acc + (size_t)o0 * DA);
    float4* ap1 = (float4*)(g_acc + (size_t)o1 * DA);
    ap0[0] = make_float4(accF0[0], accF0[1], accF0[2], accF0[3]);
    ap0[1] = make_float4(accF0[4], accF0[5], accF0[6], accF0[7]);
    ap1[0] = make_float4(accF1[0], accF1[1], accF1[2], accF1[3]);
    ap1[1] = make_float4(accF1[4], accF1[5], accF1[6], accF1[7]);
    g_sum[o0] = ssumF0;
    g_sum[o1] = ssumF1;
}

// ---------------- Kernel 3: final, 4 threads per row ----------------
__global__ __launch_bounds__(128) void final_kernel(
    const float* __restrict__ x,
    const float* __restrict__ Zw, const float* __restrict__ Zb,
    float* __restrict__ out)
{
    __shared__ float sZ[DA * DIN];
    __shared__ float sZb[DIN];
    int t = threadIdx.x;
    for (int i = t; i < DA * DIN; i += 128) sZ[i] = Zw[i];
    if (t < DIN) sZb[t] = Zb[t];
    __syncthreads();

    int gid  = blockIdx.x * 128 + t;
    int row  = gid >> 2;
    int part = gid & 3;

    float acc[DA];
#pragma unroll
    for (int a = 0; a < DA; a++) acc[a] = 0.0f;
    float ssum = 0.0f;
#pragma unroll
    for (int i = 0; i < KSPLIT / 4; i++) {
        int o = (part * (KSPLIT / 4) + i) * NROWS + row;
        ssum += g_sum[o];
        const float4* ap = (const float4*)(g_acc + (size_t)o * DA);
        float4 a0 = ap[0], a1 = ap[1];
        acc[0] += a0.x; acc[1] += a0.y; acc[2] += a0.z; acc[3] += a0.w;
        acc[4] += a1.x; acc[5] += a1.y; acc[6] += a1.z; acc[7] += a1.w;
    }
#pragma unroll
    for (int a = 0; a < DA; a++) {
        acc[a] += __shfl_xor_sync(0xFFFFFFFFu, acc[a], 1);
        acc[a] += __shfl_xor_sync(0xFFFFFFFFu, acc[a], 2);
    }
    ssum += __shfl_xor_sync(0xFFFFFFFFu, ssum, 1);
    ssum += __shfl_xor_sync(0xFFFFFFFFu, ssum, 2);

    float inv = 1.0f / ssum;
    float z[DA];
#pragma unroll
    for (int a = 0; a < DA; a++) z[a] = acc[a] * inv;

    const float4* xp = (const float4*)(x + (size_t)row * DIN) + part * 3;
    float4* op = (float4*)(out + (size_t)row * DIN) + part * 3;
#pragma unroll
    for (int c = 0; c < 3; c++) {
        int d0 = part * 12 + 4 * c;
        float4 xv = xp[c];
        float o4[4] = {xv.x + sZb[d0], xv.y + sZb[d0 + 1], xv.z + sZb[d0 + 2], xv.w + sZb[d0 + 3]};
#pragma unroll
        for (int a = 0; a < DA; a++) {
            float za = z[a];
            const float* w = &sZ[a * DIN + d0];
            o4[0] = fmaf(za, w[0], o4[0]);
            o4[1] = fmaf(za, w[1], o4[1]);
            o4[2] = fmaf(za, w[2], o4[2]);
            o4[3] = fmaf(za, w[3], o4[3]);
        }
        op[c] = make_float4(o4[0], o4[1], o4[2], o4[3]);
    }
}

extern "C" void kernel_launch(void* const* d_in, const int* in_sizes, int n_in,
                              void* d_out, int out_size)
{
    (void)in_sizes; (void)n_in; (void)out_size;
    const float* x  = (const float*)d_in[0];
    const float* Kw = (const float*)d_in[1];
    const float* Kb = (const float*)d_in[2];
    const float* Qw = (const float*)d_in[3];
    const float* Qb = (const float*)d_in[4];
    const float* Vw = (const float*)d_in[5];
    const float* Vb = (const float*)d_in[6];
    const float* Zw = (const float*)d_in[7];
    const float* Zb = (const float*)d_in[8];
    float* out = (float*)d_out;

    dim3 gp(NROWS / 64, 3);
    proj_kernel<<<gp, 256>>>(x, Kw, Kb, Qw, Qb, Vw, Vb);
    dim3 ga(NROWS / 256, KSPLIT);
    attn_kernel<<<ga, 128>>>();
    final_kernel<<<(NROWS * 4) / 128, 128>>>(x, Zw, Zb, out);
}